// round 2
// baseline (speedup 1.0000x reference)
#include <cuda_runtime.h>
#include <cstddef>

// 3D Haar wavelet (frames valid, h/w 'same' right-zero-pad), all 8 subbands fused.
// x: (2,3,16,256,256) f32. Out: LLL (2,3,15,256,256) then detail (2,3,105,256,256)
// detail subband order: LLH, LHL, LHH, HLL, HLH, HHL, HHH
//
// Each thread: one (bc, f, h, w0..w0+3) strip. Loads the 2x2 plane corners
// (f/f+1 x h/h+1) as float4 + 1 boundary scalar each, butterflies w -> h -> f,
// writes 8 float4s (one per subband). Write-bound: ~189 MB writes, ~25 MB reads.

#define NBC   6        // 2*3
#define NF    15
#define NH    256
#define NW    256
#define NW4   64       // NW/4
#define FRAME_STRIDE 65536   // 256*256
#define LLL_ELEMS 5898240    // 6*15*65536
#define S3 0.04419417382415922f  // 1/(16*sqrt(2))

__global__ void __launch_bounds__(256) haar3d_kernel(
    const float* __restrict__ x,
    float* __restrict__ out_lll,
    float* __restrict__ out_det)
{
    int idx = blockIdx.x * blockDim.x + threadIdx.x;
    // total threads = NBC*NF*NH*NW4 = 6*15*256*64 = 1,474,560
    if (idx >= NBC * NF * NH * NW4) return;

    int wv   = idx & (NW4 - 1);
    int h    = (idx >> 6) & (NH - 1);
    int rest = idx >> 14;          // bc*NF + f
    int f    = rest % NF;
    int bc   = rest / NF;
    int w0   = wv << 2;

    const float* base = x + ((size_t)(bc * 16 + f)) * FRAME_STRIDE + h * NW + w0;
    const bool wtail = (w0 + 4 >= NW);   // last strip: w0==252
    const bool hlast = (h == NH - 1);

    // corners: p[frame][height][lane 0..4]  (lane 4 = boundary scalar / zero pad)
    float p00[5], p01[5], p10[5], p11[5];

    {
        float4 v = *(const float4*)(base);
        p00[0]=v.x; p00[1]=v.y; p00[2]=v.z; p00[3]=v.w;
        p00[4] = wtail ? 0.f : base[4];
    }
    {
        float4 v = *(const float4*)(base + FRAME_STRIDE);
        p10[0]=v.x; p10[1]=v.y; p10[2]=v.z; p10[3]=v.w;
        p10[4] = wtail ? 0.f : base[FRAME_STRIDE + 4];
    }
    if (!hlast) {
        float4 v = *(const float4*)(base + NW);
        p01[0]=v.x; p01[1]=v.y; p01[2]=v.z; p01[3]=v.w;
        p01[4] = wtail ? 0.f : base[NW + 4];
        float4 u = *(const float4*)(base + FRAME_STRIDE + NW);
        p11[0]=u.x; p11[1]=u.y; p11[2]=u.z; p11[3]=u.w;
        p11[4] = wtail ? 0.f : base[FRAME_STRIDE + NW + 4];
    } else {
        #pragma unroll
        for (int k = 0; k < 5; k++) { p01[k] = 0.f; p11[k] = 0.f; }
    }

    float4 oLLL, oLLH, oLHL, oLHH, oHLL, oHLH, oHHL, oHHH;
    float* rLLL = &oLLL.x; float* rLLH = &oLLH.x;
    float* rLHL = &oLHL.x; float* rLHH = &oLHH.x;
    float* rHLL = &oHLL.x; float* rHLH = &oHLH.x;
    float* rHHL = &oHHL.x; float* rHHH = &oHHH.x;

    #pragma unroll
    for (int k = 0; k < 4; k++) {
        // w stage (low = a+b, high = b-a), per (frame, height) plane
        float wl00 = p00[k] + p00[k+1], wh00 = p00[k+1] - p00[k];
        float wl01 = p01[k] + p01[k+1], wh01 = p01[k+1] - p01[k];
        float wl10 = p10[k] + p10[k+1], wh10 = p10[k+1] - p10[k];
        float wl11 = p11[k] + p11[k+1], wh11 = p11[k+1] - p11[k];
        // h stage: per frame i, (hType, wType)
        float q0LL = wl00 + wl01, q0LH = wh00 + wh01;
        float q0HL = wl01 - wl00, q0HH = wh01 - wh00;
        float q1LL = wl10 + wl11, q1LH = wh10 + wh11;
        float q1HL = wl11 - wl10, q1HH = wh11 - wh10;
        // f stage: low = f0+f1, high = f1-f0 ; label order (F,H,W)
        rLLL[k] = S3 * (q0LL + q1LL);
        rLLH[k] = S3 * (q0LH + q1LH);
        rLHL[k] = S3 * (q0HL + q1HL);
        rLHH[k] = S3 * (q0HH + q1HH);
        rHLL[k] = S3 * (q1LL - q0LL);
        rHLH[k] = S3 * (q1LH - q0LH);
        rHHL[k] = S3 * (q1HL - q0HL);
        rHHH[k] = S3 * (q1HH - q0HH);
    }

    size_t plane = (size_t)h * NW + w0;
    // LLL: (bc, f, h, w)
    *(float4*)(out_lll + ((size_t)(bc * NF + f)) * FRAME_STRIDE + plane) = oLLL;
    // detail: (bc, s*15 + f, h, w), s in {LLH,LHL,LHH,HLL,HLH,HHL,HHH}
    size_t dbase = ((size_t)(bc * 7 * NF + f)) * FRAME_STRIDE + plane;
    *(float4*)(out_det + dbase + (size_t)0 * NF * FRAME_STRIDE) = oLLH;
    *(float4*)(out_det + dbase + (size_t)1 * NF * FRAME_STRIDE) = oLHL;
    *(float4*)(out_det + dbase + (size_t)2 * NF * FRAME_STRIDE) = oLHH;
    *(float4*)(out_det + dbase + (size_t)3 * NF * FRAME_STRIDE) = oHLL;
    *(float4*)(out_det + dbase + (size_t)4 * NF * FRAME_STRIDE) = oHLH;
    *(float4*)(out_det + dbase + (size_t)5 * NF * FRAME_STRIDE) = oHHL;
    *(float4*)(out_det + dbase + (size_t)6 * NF * FRAME_STRIDE) = oHHH;
}

extern "C" void kernel_launch(void* const* d_in, const int* in_sizes, int n_in,
                              void* d_out, int out_size)
{
    const float* x = (const float*)d_in[0];
    float* out = (float*)d_out;
    float* out_lll = out;
    float* out_det = out + LLL_ELEMS;

    const int total = NBC * NF * NH * NW4;   // 1,474,560
    const int block = 256;
    const int grid = (total + block - 1) / block;  // 5760
    haar3d_kernel<<<grid, block>>>(x, out_lll, out_det);
}